// round 17
// baseline (speedup 1.0000x reference)
#include <cuda_runtime.h>
#include <cuda_bf16.h>
#include <math.h>
#include <stdint.h>

#define TSTEPS  20
#define NLAYERS 4
#define DM      512
#define DS      128
#define ROWS    2048      // BATCH(4) * SEQ(512)
#define VOCAB   32000

// ---------------- scratch (device globals; no allocations allowed) ----------
// Spike format (byte per lane-warp): per (buf,t,row): 64 bytes. Byte (2l+s)
// belongs to lane l of sub-warp s; bit (4q+j) = spike of dim 128*(2s+q)+4l+j.
__device__ uint8_t       g_bits[2][TSTEPS][ROWS][64];
__device__ float         g_AT[NLAYERS][DS * DS];      // AT[j*DS+i] = A[i][j]
__device__ float         g_BT[NLAYERS][DM * DS];      // BT[d*DS+i] = B[i][d]
__device__ float         g_CT[NLAYERS][DS * DM];      // CT[i*DM+d] = C[d][i]
__device__ __nv_bfloat16 g_cntb[ROWS * DM];           // exact integer spike counts
__device__ __nv_bfloat16 g_wph[(size_t)VOCAB * DM];   // bf16 hi of Wp
__device__ __nv_bfloat16 g_wpl[(size_t)VOCAB * DM];   // bf16 lo of Wp

// ---------------- weight transposes ----------------------------------------
__global__ void prep_kernel(const float* __restrict__ A,
                            const float* __restrict__ Bm,
                            const float* __restrict__ Cm) {
    int stride = gridDim.x * blockDim.x;
    int gid = blockIdx.x * blockDim.x + threadIdx.x;
    for (int idx = gid; idx < NLAYERS * DS * DS; idx += stride) {
        int l = idx / (DS * DS); int rm = idx % (DS * DS);
        int i = rm / DS, j = rm % DS;
        g_AT[l][j * DS + i] = A[idx];
    }
    for (int idx = gid; idx < NLAYERS * DS * DM; idx += stride) {
        int l = idx / (DS * DM); int rm = idx % (DS * DM);
        int i = rm / DM, d = rm % DM;
        g_BT[l][d * DS + i] = Bm[idx];
    }
    for (int idx = gid; idx < NLAYERS * DM * DS; idx += stride) {
        int l = idx / (DM * DS); int rm = idx % (DM * DS);
        int d = rm / DS, i = rm % DS;
        g_CT[l][i * DM + d] = Cm[idx];
    }
}

// ---------------- Wp two-term bf16 split ------------------------------------
__global__ void split_wp_kernel(const float* __restrict__ Wp) {
    long long i = (long long)blockIdx.x * blockDim.x + threadIdx.x;
    if (i >= (long long)VOCAB * DM) return;
    float w = Wp[i];
    __nv_bfloat16 h = __float2bfloat16(w);
    g_wph[i] = h;
    g_wpl[i] = __float2bfloat16(w - __bfloat162float(h));
}

__global__ void zero_bits_kernel() {
    int gid = blockIdx.x * blockDim.x + threadIdx.x;
    uint32_t* p = (uint32_t*)&g_bits[0][0][0][0];
    int n = TSTEPS * ROWS * 16;          // buffer 0 (encode's atomicOr target)
    for (int i = gid; i < n; i += gridDim.x * blockDim.x) p[i] = 0u;
}

// ---------------- temporal encoding (exact fp32 logistic, as validated) -----
// Emits the byte-per-(lane,warp) spike format directly.
__global__ void encode_kernel(const int* __restrict__ ids,
                              const float* __restrict__ emb) {
    int gid = blockIdx.x * blockDim.x + threadIdx.x;
    if (gid >= ROWS * DM) return;
    int r = gid >> 9, d = gid & (DM - 1);
    float x = emb[(long long)ids[r] * DM + d];
    float sgf = 1.0f / (1.0f + expf(-x));
    int t = (int)floorf(sgf * 19.0f);
    if (t < 0) t = 0;
    if (t > 19) t = 19;
    int k = d >> 7, rem = d & 127, l = rem >> 2, j = rem & 3;
    int s = k >> 1, q = k & 1;
    int byte_idx = 2 * l + s;
    int bit = 4 * q + j;
    uint32_t* wp32 = (uint32_t*)&g_bits[0][t][r][0] + (byte_idx >> 2);
    atomicOr(wp32, 1u << ((byte_idx & 3) * 8 + bit));
}

// ---------------- LIF-SSM layer: TWO WARPS PER ROW ---------------------------
// Warp s of the pair owns state dims {64s+2l, 64s+2l+1} (float2 A/B gathers)
// and output k-blocks {2s, 2s+1} with dims 128k+4l+j (float4 C-gathers).
// x-list: 4 fixed-capacity segments (128 ints each, segment k at offset 128k);
// warp s builds segments 2s,2s+1 from its own spike byte. Iterating segments
// k=0..3 keeps ascending-dim order -> accumulation sequence identical to the
// validated kernel (bit-exact trajectory). h-list: 2 segments of 64.
// Pair-private named barriers (bar.sync 1+pair, 64):
//   B1 : x segments + counts visible, prior-timestep gathers complete
//   B2a: both warps done with A/B gathers (old hlist consumed)
//   B2b: new hlist + counts visible before C-gather
// last!=0: counts accumulate in registers; writes g_cntb, not g_bits.
#define ROWBAR(p) asm volatile("bar.sync %0, 64;" :: "r"((p) + 1) : "memory")

__global__ __launch_bounds__(256) void ssm_warp2_kernel(int layer, int inb, int outb,
                                                        const float* __restrict__ Dfull,
                                                        int last) {
    int tid  = threadIdx.x;
    int wrp  = tid >> 5, lane = tid & 31;
    int pair = wrp >> 1, s = wrp & 1;
    int r    = blockIdx.x * 4 + pair;
    const float* __restrict__ AT = g_AT[layer];
    const float* __restrict__ BT = g_BT[layer];
    const float* __restrict__ CT = g_CT[layer];
    const float* __restrict__ Dv = Dfull + layer * DM;

    __shared__ int sxidx[4][512];
    __shared__ int shidx[4][128];
    __shared__ int snx[4][4];
    __shared__ int snh[4][2];
    int* xlist = sxidx[pair];
    int* hlist = shidx[pair];

    int d0 = 64 * s + 2 * lane;            // this thread's two state dims
    int k0 = 2 * s, k1 = 2 * s + 1;        // this warp's output k-blocks

    float4 dv4[2];
    dv4[0] = *(const float4*)(Dv + 128 * k0 + 4 * lane);
    dv4[1] = *(const float4*)(Dv + 128 * k1 + 4 * lane);

    float v1a = 0.f, v1b = 0.f;
    float v2[2][4] = {};
    float cnt[2][4] = {};
    if (tid < 8) snh[tid >> 1][tid & 1] = 0;
    __syncthreads();

    uint32_t xb = g_bits[inb][0][r][2 * lane + s];

    for (int t = 0; t < TSTEPS; t++) {
        uint32_t fl = xb;                  // 8 flag bits: 4q+j for k=2s+q

        // ---- build x segments k0,k1 (ascending dims within each) ----
        uint32_t c0 = __popc(fl & 0xFu);
        uint32_t c1 = __popc((fl >> 4) & 0xFu);
        uint32_t packed = c0 | (c1 << 8);
        uint32_t incl = packed;
        #pragma unroll
        for (int off = 1; off < 32; off <<= 1) {
            uint32_t y = __shfl_up_sync(0xffffffffu, incl, off);
            if (lane >= off) incl += y;
        }
        uint32_t tot = __shfl_sync(0xffffffffu, incl, 31);
        uint32_t excl = incl - packed;
        int pos0 = 128 * k0 + (int)(excl & 0xFF);
        int pos1 = 128 * k1 + (int)((excl >> 8) & 0xFF);
        uint32_t f0 = fl & 0xFu, f1 = (fl >> 4) & 0xFu;
        #pragma unroll
        for (int j = 0; j < 4; j++)
            if ((f0 >> j) & 1u) xlist[pos0++] = (128 * k0 + 4 * lane + j) * DS;
        #pragma unroll
        for (int j = 0; j < 4; j++)
            if ((f1 >> j) & 1u) xlist[pos1++] = (128 * k1 + 4 * lane + j) * DS;
        if (lane == 0) {
            snx[pair][k0] = (int)(tot & 0xFF);
            snx[pair][k1] = (int)((tot >> 8) & 0xFF);
        }
        ROWBAR(pair);                      // B1

        if (t + 1 < TSTEPS) xb = g_bits[inb][t + 1][r][2 * lane + s];

        // ---- state_update: round(h@A^T) + round(x@B^T), ascending ----
        float sa0 = 0.f, sa1 = 0.f;
        #pragma unroll 1
        for (int q = 0; q < 2; q++) {
            int nq = snh[pair][q];
            #pragma unroll 4
            for (int i = 0; i < nq; i++) {
                float2 av = *(const float2*)(AT + hlist[64 * q + i] + d0);
                sa0 += av.x; sa1 += av.y;
            }
        }
        float sb0 = 0.f, sb1 = 0.f;
        #pragma unroll 1
        for (int k = 0; k < 4; k++) {
            int nk = snx[pair][k];
            const int* seg = xlist + 128 * k;
            #pragma unroll 4
            for (int i = 0; i < nk; i++) {
                float2 bv = *(const float2*)(BT + seg[i] + d0);
                sb0 += bv.x; sb1 += bv.y;
            }
        }
        float u0 = sa0 + sb0, u1 = sa1 + sb1;

        // ---- LIF1 ----
        v1a = v1a + (u0 - v1a) * 0.5f;
        v1b = v1b + (u1 - v1b) * 0.5f;
        int s1a = (v1a - 1.0f) >= 0.f;
        int s1b = (v1b - 1.0f) >= 0.f;
        if (s1a) v1a = 0.f;
        if (s1b) v1b = 0.f;
        ROWBAR(pair);                      // B2a: old hlist fully consumed

        // build h segment s (dims 64s+2l+{0,1}, ascending)
        int ch = s1a + s1b;
        uint32_t hincl = (uint32_t)ch;
        #pragma unroll
        for (int off = 1; off < 32; off <<= 1) {
            uint32_t y = __shfl_up_sync(0xffffffffu, hincl, off);
            if (lane >= off) hincl += y;
        }
        int hpos = 64 * s + (int)hincl - ch;
        if (s1a) hlist[hpos++] = (d0 + 0) * DS;
        if (s1b) hlist[hpos++] = (d0 + 1) * DS;
        if (lane == 31) snh[pair][s] = (int)hincl;
        ROWBAR(pair);                      // B2b: hlist + counts visible

        // ---- output_update: round(h@C^T) + x*D, ascending ----
        float sc[2][4] = {};
        #pragma unroll 1
        for (int q = 0; q < 2; q++) {
            int nq = snh[pair][q];
            #pragma unroll 2
            for (int i = 0; i < nq; i++) {
                const float* crow = CT + (hlist[64 * q + i] << 2) + 4 * lane;
                float4 cv0 = *(const float4*)(crow + 128 * k0);
                float4 cv1 = *(const float4*)(crow + 128 * k1);
                sc[0][0] += cv0.x; sc[0][1] += cv0.y;
                sc[0][2] += cv0.z; sc[0][3] += cv0.w;
                sc[1][0] += cv1.x; sc[1][1] += cv1.y;
                sc[1][2] += cv1.z; sc[1][3] += cv1.w;
            }
        }

        // ---- LIF2 + output ----
        uint32_t of = 0;
        #pragma unroll
        for (int q = 0; q < 2; q++) {
            float dvk[4] = {dv4[q].x, dv4[q].y, dv4[q].z, dv4[q].w};
            #pragma unroll
            for (int j = 0; j < 4; j++) {
                float u2 = sc[q][j];
                if ((fl >> (4 * q + j)) & 1u) u2 = u2 + dvk[j];
                v2[q][j] = v2[q][j] + (u2 - v2[q][j]) * 0.5f;
                int s2 = (v2[q][j] - 1.0f) >= 0.f;
                if (s2) of |= 1u << (4 * q + j);
                if (!last) { if (s2) v2[q][j] = 0.f; }
                else       { cnt[q][j] += s2 ? 1.0f : 0.0f; if (s2) v2[q][j] = 0.f; }
            }
        }
        if (!last) g_bits[outb][t][r][2 * lane + s] = (uint8_t)of;
    }

    if (last) {
        #pragma unroll
        for (int q = 0; q < 2; q++)
            #pragma unroll
            for (int j = 0; j < 4; j++)
                g_cntb[(size_t)r * DM + 128 * (2 * s + q) + 4 * lane + j] =
                    __float2bfloat16(cnt[q][j]);
    }
}

// ============ logits GEMM: split-bf16 mma.sync + ldmatrix, 3-stage cp.async ==
#define SPAD   40                        // bf16 per smem row (80 B pitch)
#define KC     32                        // K per chunk
#define NCH    (DM / KC)                 // 16 chunks
#define ST     3                         // pipeline stages
#define MAT_B  (128 * SPAD * 2)          // 10240 B per matrix tile
#define STAGE_B (3 * MAT_B)              // A + Bh + Bl
#define GSMEM_BYTES (ST * STAGE_B)       // 92160

__device__ __forceinline__ void mma16816(float* d, const uint32_t* a, const uint32_t* b) {
    asm volatile(
        "mma.sync.aligned.m16n8k16.row.col.f32.bf16.bf16.f32 "
        "{%0,%1,%2,%3}, {%4,%5,%6,%7}, {%8,%9}, {%0,%1,%2,%3};"
        : "+f"(d[0]), "+f"(d[1]), "+f"(d[2]), "+f"(d[3])
        : "r"(a[0]), "r"(a[1]), "r"(a[2]), "r"(a[3]), "r"(b[0]), "r"(b[1]));
}
__device__ __forceinline__ void ldmx4(uint32_t* r, uint32_t a) {
    asm volatile("ldmatrix.sync.aligned.m8n8.x4.shared.b16 {%0,%1,%2,%3}, [%4];"
        : "=r"(r[0]), "=r"(r[1]), "=r"(r[2]), "=r"(r[3]) : "r"(a));
}
__device__ __forceinline__ void ldmx2(uint32_t* r, uint32_t a) {
    asm volatile("ldmatrix.sync.aligned.m8n8.x2.shared.b16 {%0,%1}, [%2];"
        : "=r"(r[0]), "=r"(r[1]) : "r"(a));
}
__device__ __forceinline__ void cpasync16(uint32_t dst, const void* src) {
    asm volatile("cp.async.ca.shared.global [%0], [%1], 16;" :: "r"(dst), "l"(src));
}
__device__ __forceinline__ uint32_t smem_u32(const void* p) {
    uint32_t a;
    asm("{ .reg .u64 t; cvta.to.shared.u64 t, %1; cvt.u32.u64 %0, t; }"
        : "=r"(a) : "l"(p));
    return a;
}

__global__ __launch_bounds__(256, 2) void gemm_bf16_kernel(const float* __restrict__ bp,
                                                           float* __restrict__ out) {
    extern __shared__ char smem[];
    uint32_t sbase = smem_u32(smem);

    int bm = blockIdx.x, bn = blockIdx.y;   // bm fastest -> Wp tile reused in L2
    int tid = threadIdx.x;
    int w   = tid >> 5;
    int wm  = w >> 2, wn = w & 3;           // 2 x 4 warps
    int lane = tid & 31;
    int g = lane >> 2, tig = lane & 3;

    const __nv_bfloat16* asrc = g_cntb + (size_t)(bm * 128) * DM;
    const __nv_bfloat16* hsrc = g_wph  + (size_t)(bn * 128) * DM;
    const __nv_bfloat16* lsrc = g_wpl  + (size_t)(bn * 128) * DM;

    int a_q = lane >> 3, a_r = lane & 7;
    uint32_t a_off = (uint32_t)(((wm * 64 + (a_q & 1) * 8 + a_r) * SPAD +
                                 (a_q >> 1) * 8) * 2);
    int b_r = lane & 7, b_q = (lane >> 3) & 1;
    uint32_t b_off = (uint32_t)(((wn * 32 + b_r) * SPAD + b_q * 8) * 2);

    int crow  = tid >> 1;
    int chalf = (tid & 1) * 32;

    auto issue_stage = [&](int s, int c) {
        uint32_t dbase = sbase + s * STAGE_B + crow * (SPAD * 2) + chalf;
        size_t goff = (size_t)crow * DM + c * KC + (chalf >> 1);
        cpasync16(dbase,                  asrc + goff);
        cpasync16(dbase + 16,             asrc + goff + 8);
        cpasync16(dbase + MAT_B,          hsrc + goff);
        cpasync16(dbase + MAT_B + 16,     hsrc + goff + 8);
        cpasync16(dbase + 2 * MAT_B,      lsrc + goff);
        cpasync16(dbase + 2 * MAT_B + 16, lsrc + goff + 8);
    };

    #pragma unroll
    for (int s = 0; s < ST - 1; s++) {
        issue_stage(s, s);
        asm volatile("cp.async.commit_group;" ::: "memory");
    }

    float acc[4][4][4];
    #pragma unroll
    for (int i = 0; i < 4; i++)
        #pragma unroll
        for (int j = 0; j < 4; j++)
            #pragma unroll
            for (int q = 0; q < 4; q++) acc[i][j][q] = 0.f;

    #pragma unroll 1
    for (int c = 0; c < NCH; c++) {
        if (c < NCH - 1) asm volatile("cp.async.wait_group 1;" ::: "memory");
        else             asm volatile("cp.async.wait_group 0;" ::: "memory");
        __syncthreads();

        if (c + 2 < NCH) {
            issue_stage((c + 2) % ST, c + 2);
            asm volatile("cp.async.commit_group;" ::: "memory");
        }

        uint32_t st = sbase + (c % ST) * STAGE_B;

        #pragma unroll
        for (int ks = 0; ks < KC / 16; ks++) {
            uint32_t kof = (uint32_t)(ks * 16 * 2);
            uint32_t afr[4][4];
            #pragma unroll
            for (int mf = 0; mf < 4; mf++)
                ldmx4(afr[mf], st + a_off + (uint32_t)(mf * 16 * SPAD * 2) + kof);
            #pragma unroll
            for (int nf = 0; nf < 4; nf++) {
                uint32_t bof = b_off + (uint32_t)(nf * 8 * SPAD * 2) + kof;
                uint32_t bh[2], bl[2];
                ldmx2(bh, st + MAT_B + bof);
                ldmx2(bl, st + 2 * MAT_B + bof);
                #pragma unroll
                for (int mf = 0; mf < 4; mf++) {
                    mma16816(acc[mf][nf], afr[mf], bh);
                    mma16816(acc[mf][nf], afr[mf], bl);
                }
            }
        }
        __syncthreads();
    }

    #pragma unroll
    for (int nf = 0; nf < 4; nf++) {
        int col = bn * 128 + wn * 32 + nf * 8 + 2 * tig;
        float2 bias = *(const float2*)(bp + col);
        #pragma unroll
        for (int mf = 0; mf < 4; mf++) {
            int row0 = bm * 128 + wm * 64 + mf * 16 + g;
            float2 o0, o1;
            o0.x = acc[mf][nf][0] * 0.05f + bias.x;
            o0.y = acc[mf][nf][1] * 0.05f + bias.y;
            o1.x = acc[mf][nf][2] * 0.05f + bias.x;
            o1.y = acc[mf][nf][3] * 0.05f + bias.y;
            *(float2*)(out + (size_t)row0 * VOCAB + col)       = o0;
            *(float2*)(out + (size_t)(row0 + 8) * VOCAB + col) = o1;
        }
    }
}

// ---------------- launch -----------------------------------------------------
// ssm layer-0 stays at launch slot #4 so the profiler keeps reporting it.
extern "C" void kernel_launch(void* const* d_in, const int* in_sizes, int n_in,
                              void* d_out, int out_size) {
    const int*   ids  = (const int*)d_in[0];
    const float* emb  = (const float*)d_in[1];
    const float* A    = (const float*)d_in[2];
    const float* Bm   = (const float*)d_in[3];
    const float* Cm   = (const float*)d_in[4];
    const float* Dm_  = (const float*)d_in[5];
    const float* Wp   = (const float*)d_in[6];
    const float* bp   = (const float*)d_in[7];
    float*       out  = (float*)d_out;

    prep_kernel<<<256, 256>>>(A, Bm, Cm);
    zero_bits_kernel<<<256, 256>>>();
    encode_kernel<<<(ROWS * DM + 255) / 256, 256>>>(ids, emb);

    ssm_warp2_kernel<<<ROWS / 4, 256>>>(0, 0, 1, Dm_, 0);   // launch #4 -> profiled
    ssm_warp2_kernel<<<ROWS / 4, 256>>>(1, 1, 0, Dm_, 0);
    ssm_warp2_kernel<<<ROWS / 4, 256>>>(2, 0, 1, Dm_, 0);
    ssm_warp2_kernel<<<ROWS / 4, 256>>>(3, 1, 0, Dm_, 1);   // fused count -> g_cntb

    split_wp_kernel<<<(VOCAB * DM + 255) / 256, 256>>>(Wp);

    cudaFuncSetAttribute(gemm_bf16_kernel,
                         cudaFuncAttributeMaxDynamicSharedMemorySize,
                         GSMEM_BYTES);
    gemm_bf16_kernel<<<dim3(ROWS / 128, VOCAB / 128), 256, GSMEM_BYTES>>>(bp, out);
}